// round 7
// baseline (speedup 1.0000x reference)
#include <cuda_runtime.h>
#include <cuda_bf16.h>
#include <cstdint>

#define SS 2048
#define HH 4096
#define NHH 32
#define HDD 128
#define K2 8192
#define INV_NORM 0.088388347648318447f   // 1/sqrt(128)

// ---------------- scratch (__device__ globals; no allocs allowed) ----------------
__device__ __nv_bfloat16 g_qhi[16777216];   // [B,NH,S,HD] (pre-scaled by INV_NORM)
__device__ __nv_bfloat16 g_qlo[16777216];
__device__ __nv_bfloat16 g_khi[16777216];
__device__ __nv_bfloat16 g_klo[16777216];
__device__ __nv_bfloat16 g_vhi[16777216];
__device__ __nv_bfloat16 g_vlo[16777216];
__device__ __nv_bfloat16 g_A2[(size_t)4096 * K2];    // hidden  [hi|lo]
__device__ __nv_bfloat16 g_W2[(size_t)12288 * K2];   // W_qkv   [hi|lo]
__device__ __nv_bfloat16 g_Wd2[(size_t)4096 * K2];   // W_dense [hi|lo]
__device__ __nv_bfloat16 g_C2[(size_t)4096 * K2];    // ctx     [hi|lo]

// ---------------- PTX helpers ----------------
__device__ __forceinline__ uint32_t smem_u32(const void* p) {
    uint32_t a;
    asm("{ .reg .u64 t; cvta.to.shared.u64 t, %1; cvt.u32.u64 %0, t; }" : "=r"(a) : "l"(p));
    return a;
}
#define CP_ASYNC16(dst, src) \
    asm volatile("cp.async.cg.shared.global [%0], [%1], 16;" :: "r"(dst), "l"(src))
#define CP_COMMIT() asm volatile("cp.async.commit_group;" ::: "memory")
#define CP_WAIT2()  asm volatile("cp.async.wait_group 2;" ::: "memory")
#define CP_WAIT1()  asm volatile("cp.async.wait_group 1;" ::: "memory")
#define CP_WAIT0()  asm volatile("cp.async.wait_group 0;" ::: "memory")

__device__ __forceinline__ void ldsm4(uint32_t* r, uint32_t addr) {
    asm volatile("ldmatrix.sync.aligned.m8n8.x4.shared.b16 {%0,%1,%2,%3}, [%4];"
        : "=r"(r[0]), "=r"(r[1]), "=r"(r[2]), "=r"(r[3]) : "r"(addr));
}
__device__ __forceinline__ void ldsm4t(uint32_t* r, uint32_t addr) {
    asm volatile("ldmatrix.sync.aligned.m8n8.x4.trans.shared.b16 {%0,%1,%2,%3}, [%4];"
        : "=r"(r[0]), "=r"(r[1]), "=r"(r[2]), "=r"(r[3]) : "r"(addr));
}
__device__ __forceinline__ void mma16816(float* c, const uint32_t* a, const uint32_t* b) {
    asm volatile(
        "mma.sync.aligned.m16n8k16.row.col.f32.bf16.bf16.f32 "
        "{%0,%1,%2,%3}, {%4,%5,%6,%7}, {%8,%9}, {%0,%1,%2,%3};"
        : "+f"(c[0]), "+f"(c[1]), "+f"(c[2]), "+f"(c[3])
        : "r"(a[0]), "r"(a[1]), "r"(a[2]), "r"(a[3]), "r"(b[0]), "r"(b[1]));
}
__device__ __forceinline__ uint32_t pack_bf16(__nv_bfloat16 a, __nv_bfloat16 b) {
    return (uint32_t)__bfloat16_as_ushort(a) | ((uint32_t)__bfloat16_as_ushort(b) << 16);
}

// ====================================================================
// fp32 [R][4096] -> bf16 [R][8192] as [hi | lo]
// ====================================================================
template<int WHICH>
__global__ void convert_kernel(const float* __restrict__ src) {
    size_t i = (size_t)blockIdx.x * 256 + threadIdx.x;  // one float4 per thread
    size_t r = i >> 10;
    int c = (int)(i & 1023) * 4;
    float4 v = *(const float4*)(src + (r << 12) + c);
    float f[4] = {v.x, v.y, v.z, v.w};
    unsigned short h[4], l[4];
#pragma unroll
    for (int j = 0; j < 4; j++) {
        __nv_bfloat16 hb = __float2bfloat16(f[j]);
        __nv_bfloat16 lb = __float2bfloat16(f[j] - __bfloat162float(hb));
        h[j] = __bfloat16_as_ushort(hb);
        l[j] = __bfloat16_as_ushort(lb);
    }
    uint2 hp = make_uint2((uint32_t)h[0] | ((uint32_t)h[1] << 16),
                          (uint32_t)h[2] | ((uint32_t)h[3] << 16));
    uint2 lp = make_uint2((uint32_t)l[0] | ((uint32_t)l[1] << 16),
                          (uint32_t)l[2] | ((uint32_t)l[3] << 16));
    __nv_bfloat16* dst = (WHICH == 0) ? g_A2 : (WHICH == 1) ? g_W2 : g_Wd2;
    __nv_bfloat16* base = dst + r * K2 + c;
    *(uint2*)(base) = hp;
    *(uint2*)(base + 4096) = lp;
}

// ====================================================================
// Multistage mma.sync bf16 GEMM, 3-term compensation via chunk remap.
// Tile 128x256, warp 64x64 (8 warps), BK=32, 4 stages, 1 sync/chunk.
// Chunks (BK=32, NCH=384):
//   c <  128 : hi.hi  (ak=c,      wk=c)
//   128..255 : lo.hi  (ak=c,      wk=c-128)
//   256..383 : hi.lo  (ak=c-256,  wk=c-128)
// MODE 0: scatter (+bias) to bf16 q/k/v hi+lo.  MODE 1: out+=bias+residual.
// ====================================================================
#define ROWB 80                    // 64B data + 16B pad (16B-aligned, conflict-free)
#define BOFF (128 * ROWB)          // B rows start (smem rows 128..383)
#define STAGEB (384 * ROWB)        // 30720
#define NSTAGE 4
#define GSM_TOTAL (NSTAGE * STAGEB)   // 122880
#define NCH 384

__device__ __forceinline__ int ak_of(int c) { return c & 255; }
__device__ __forceinline__ int wk_of(int c) { return (c < 128) ? c : c - 128; }

__device__ __forceinline__ void load_chunk32(uint32_t sbuf,
    const __nv_bfloat16* Abase, const __nv_bfloat16* Wbase,
    int ak, int wk, int tid)
{
#pragma unroll
    for (int i = 0; i < 2; i++) {           // A: rows 0..127
        const int idx = tid + i * 256;
        const int row = idx >> 2;
        const int seg = idx & 3;
        CP_ASYNC16(sbuf + row * ROWB + seg * 16,
                   Abase + (size_t)row * K2 + ak * 32 + seg * 8);
    }
#pragma unroll
    for (int i = 2; i < 6; i++) {           // B: rows 0..255 at BOFF
        const int idx = tid + i * 256;
        const int row = (idx >> 2) - 128;
        const int seg = idx & 3;
        CP_ASYNC16(sbuf + BOFF + row * ROWB + seg * 16,
                   Wbase + (size_t)row * K2 + wk * 32 + seg * 8);
    }
}

template<int MODE>
__global__ __launch_bounds__(256) void hgemm_kernel(
    const float* __restrict__ bias, const float* __restrict__ residual,
    float* __restrict__ out)
{
    extern __shared__ char smem[];
    const uint32_t sb = smem_u32(smem);
    const int tid = threadIdx.x;
    const int wid = tid >> 5;
    const int lane = tid & 31;
    const int wm = (wid >> 2) * 64;       // 2 m-warp groups
    const int wnn = (wid & 3) * 64;       // 4 n-warp groups

    // supertiled rasterization: groups of 16 M-tiles, N-major inside
    constexpr int TN = (MODE == 0) ? 48 : 16;
    const int id = blockIdx.x;
    const int g = id / (16 * TN);
    const int inner = id - g * (16 * TN);
    const int bm = (g * 16 + (inner & 15)) * 128;
    const int bn = (inner >> 4) * 256;

    const __nv_bfloat16* Abase = ((MODE == 0) ? g_A2 : g_C2) + (size_t)bm * K2;
    const __nv_bfloat16* Wbase = ((MODE == 0) ? g_W2 : g_Wd2) + (size_t)bn * K2;

    float acc[4][8][4];
#pragma unroll
    for (int mt = 0; mt < 4; mt++)
#pragma unroll
        for (int nt = 0; nt < 8; nt++)
#pragma unroll
            for (int r = 0; r < 4; r++) acc[mt][nt][r] = 0.0f;

    // prologue: stages 0..2
    load_chunk32(sb + 0 * STAGEB, Abase, Wbase, ak_of(0), wk_of(0), tid); CP_COMMIT();
    load_chunk32(sb + 1 * STAGEB, Abase, Wbase, ak_of(1), wk_of(1), tid); CP_COMMIT();
    load_chunk32(sb + 2 * STAGEB, Abase, Wbase, ak_of(2), wk_of(2), tid); CP_COMMIT();

#pragma unroll 1
    for (int c = 0; c < NCH; c++) {
        CP_WAIT2();                 // chunk c landed
        __syncthreads();            // all warps done computing chunk c-1
        const int cn = c + 3;
        if (cn < NCH) {             // slot (c+3)&3 == (c-1)&3: freed by the barrier
            load_chunk32(sb + (cn & 3) * STAGEB, Abase, Wbase, ak_of(cn), wk_of(cn), tid);
            CP_COMMIT();
        }
        const uint32_t buf = sb + (c & 3) * STAGEB;
#pragma unroll
        for (int ks = 0; ks < 2; ks++) {
            uint32_t afr[4][4], bfr[4][4];
#pragma unroll
            for (int mt = 0; mt < 4; mt++) {
                const uint32_t addr = buf +
                    (wm + mt * 16 + ((lane >> 3) & 1) * 8 + (lane & 7)) * ROWB +
                    ks * 32 + ((lane >> 4) & 1) * 16;
                ldsm4(afr[mt], addr);
            }
#pragma unroll
            for (int bi = 0; bi < 4; bi++) {
                const uint32_t addr = buf + BOFF +
                    (wnn + bi * 16 + ((lane >> 4) & 1) * 8 + (lane & 7)) * ROWB +
                    ks * 32 + ((lane >> 3) & 1) * 16;
                ldsm4(bfr[bi], addr);
            }
#pragma unroll
            for (int mt = 0; mt < 4; mt++)
#pragma unroll
                for (int nt = 0; nt < 8; nt++)
                    mma16816(acc[mt][nt], afr[mt], &bfr[nt >> 1][(nt & 1) * 2]);
        }
    }

    // ---------------- epilogue ----------------
    const int gq = lane >> 2;
    const int tq = lane & 3;
    if (MODE == 0) {
#pragma unroll
        for (int nt = 0; nt < 8; nt++) {
            const int n0 = bn + wnn + nt * 8 + tq * 2;
            const int sec = (n0 >> 7) % 3;           // 0=q,1=k,2=v
            const int nh = n0 / 384;
            const int d = n0 & 127;
            const float scale = (sec == 0) ? INV_NORM : 1.0f;
            __nv_bfloat16* dhi = (sec == 0) ? g_qhi : (sec == 1) ? g_khi : g_vhi;
            __nv_bfloat16* dlo = (sec == 0) ? g_qlo : (sec == 1) ? g_klo : g_vlo;
            const float2 bv = *(const float2*)(bias + n0);
#pragma unroll
            for (int mt = 0; mt < 4; mt++) {
                const int m0 = bm + wm + mt * 16 + gq;
#pragma unroll
                for (int half = 0; half < 2; half++) {
                    const int m = m0 + half * 8;
                    const int b_ = m >> 11, s_ = m & 2047;
                    const size_t idx = (((size_t)(b_ * NHH + nh) * SS + s_) << 7) + d;
                    float v0 = (acc[mt][nt][half * 2 + 0] + bv.x) * scale;
                    float v1 = (acc[mt][nt][half * 2 + 1] + bv.y) * scale;
                    __nv_bfloat16 h0 = __float2bfloat16(v0);
                    __nv_bfloat16 h1 = __float2bfloat16(v1);
                    __nv_bfloat16 l0 = __float2bfloat16(v0 - __bfloat162float(h0));
                    __nv_bfloat16 l1 = __float2bfloat16(v1 - __bfloat162float(h1));
                    *(uint32_t*)(dhi + idx) = pack_bf16(h0, h1);
                    *(uint32_t*)(dlo + idx) = pack_bf16(l0, l1);
                }
            }
        }
    } else {
#pragma unroll
        for (int mt = 0; mt < 4; mt++) {
            const int m0 = bm + wm + mt * 16 + gq;
#pragma unroll
            for (int nt = 0; nt < 8; nt++) {
                const int n0 = bn + wnn + nt * 8 + tq * 2;
                const float2 bv = *(const float2*)(bias + n0);
                {
                    const size_t i0 = (size_t)m0 * HH + n0;
                    const float2 rv = *(const float2*)(residual + i0);
                    *(float2*)(out + i0) = make_float2(acc[mt][nt][0] + bv.x + rv.x,
                                                       acc[mt][nt][1] + bv.y + rv.y);
                }
                {
                    const size_t i1 = (size_t)(m0 + 8) * HH + n0;
                    const float2 rv = *(const float2*)(residual + i1);
                    *(float2*)(out + i1) = make_float2(acc[mt][nt][2] + bv.x + rv.x,
                                                       acc[mt][nt][3] + bv.y + rv.y);
                }
            }
        }
    }
}

// ====================================================================
// Tensor-core causal flash attention with ALiBi — fully compensated.
// (unchanged from R6 — passing at rel_err 4.2e-5)
// ====================================================================
#define ATROW 272                       // 128 bf16 + 8 pad = 272 bytes
#define SQ_HI 0
#define SQ_LO (128 * ATROW)             // 34816
#define SBUF0 (2 * 128 * ATROW)         // 69632
#define SK_HI 0
#define SK_LO (64 * ATROW)
#define SV_HI (2 * 64 * ATROW)
#define SV_LO (3 * 64 * ATROW)
#define SBUF_SZ (4 * 64 * ATROW)        // 69632
#define ATT_SMEM (SBUF0 + 2 * SBUF_SZ)  // 208896

__device__ __forceinline__ void attn_load_kv(uint32_t sbuf, int bh, int kb, int tid)
{
    const int row = tid >> 2;           // 0..63
    const int off = (tid & 3) * 64;     // byte offset
    const size_t gidx = ((size_t)bh * SS + (size_t)kb * 64 + row) * HDD + (off >> 1);
    const uint32_t dbase = sbuf + row * ATROW + off;
#pragma unroll
    for (int i = 0; i < 4; i++) CP_ASYNC16(dbase + SK_HI + i * 16, g_khi + gidx + i * 8);
#pragma unroll
    for (int i = 0; i < 4; i++) CP_ASYNC16(dbase + SK_LO + i * 16, g_klo + gidx + i * 8);
#pragma unroll
    for (int i = 0; i < 4; i++) CP_ASYNC16(dbase + SV_HI + i * 16, g_vhi + gidx + i * 8);
#pragma unroll
    for (int i = 0; i < 4; i++) CP_ASYNC16(dbase + SV_LO + i * 16, g_vlo + gidx + i * 8);
}

__global__ __launch_bounds__(256) void attn_kernel(const float* __restrict__ alibi)
{
    extern __shared__ char smem[];
    const uint32_t sb = smem_u32(smem);
    const int tid = threadIdx.x;
    const int lane = tid & 31;
    const int wid = tid >> 5;
    const int wq = wid * 16;
    const int qb = (int)gridDim.x - 1 - (int)blockIdx.x;   // heavy CTAs first
    const int bh = blockIdx.y;
    const int b_ = bh >> 5;
    const int nh = bh & 31;

    const float* alrow = alibi + (size_t)bh * SS;

    // load Q tile (hi+lo), 128 rows x 256B
    {
        const int row = tid >> 1;
        const int off = (tid & 1) * 128;
        const size_t gidx = ((size_t)bh * SS + (size_t)qb * 128 + row) * HDD + (off >> 1);
        const uint32_t dq = sb + row * ATROW + off;
#pragma unroll
        for (int i = 0; i < 8; i++) CP_ASYNC16(dq + SQ_HI + i * 16, g_qhi + gidx + i * 8);
#pragma unroll
        for (int i = 0; i < 8; i++) CP_ASYNC16(dq + SQ_LO + i * 16, g_qlo + gidx + i * 8);
    }
    attn_load_kv(sb + SBUF0, bh, 0, tid);
    CP_COMMIT();

    const int kbmax = 2 * qb + 1;
    float m0 = -1e30f, m1 = -1e30f, l0 = 0.0f, l1 = 0.0f;
    float acc[16][4];
#pragma unroll
    for (int nt = 0; nt < 16; nt++)
#pragma unroll
        for (int r = 0; r < 4; r++) acc[nt][r] = 0.0f;

    const int gq = lane >> 2, tq = lane & 3;
    const int q0 = qb * 128 + wq + gq;
    const int q1 = q0 + 8;

#pragma unroll 1
    for (int kb = 0; kb <= kbmax; kb++) {
        if (kb < kbmax) {
            attn_load_kv(sb + SBUF0 + ((kb + 1) & 1) * SBUF_SZ, bh, kb + 1, tid);
            CP_COMMIT();
            CP_WAIT1();
        } else {
            CP_WAIT0();
        }
        __syncthreads();

        const uint32_t kbuf = sb + SBUF0 + (kb & 1) * SBUF_SZ;

        // ---- QK^T (compensated) ----
        float cs[8][4];
#pragma unroll
        for (int nt = 0; nt < 8; nt++)
#pragma unroll
            for (int r = 0; r < 4; r++) cs[nt][r] = 0.0f;

#pragma unroll
        for (int ks = 0; ks < 8; ks++) {
            uint32_t ah[4], alr[4];
            const uint32_t aaddr = sb +
                (wq + ((lane >> 3) & 1) * 8 + (lane & 7)) * ATROW +
                ks * 32 + ((lane >> 4) & 1) * 16;
            ldsm4(ah, aaddr + SQ_HI);
            ldsm4(alr, aaddr + SQ_LO);
#pragma unroll
            for (int g = 0; g < 4; g++) {
                uint32_t kh[4], kl[4];
                const uint32_t baddr = kbuf +
                    (g * 16 + ((lane >> 4) & 1) * 8 + (lane & 7)) * ATROW +
                    ks * 32 + ((lane >> 3) & 1) * 16;
                ldsm4(kh, baddr + SK_HI);
                ldsm4(kl, baddr + SK_LO);
                mma16816(cs[g * 2], ah, kh);
                mma16816(cs[g * 2], alr, kh);
                mma16816(cs[g * 2], ah, kl);
                mma16816(cs[g * 2 + 1], ah, kh + 2);
                mma16816(cs[g * 2 + 1], alr, kh + 2);
                mma16816(cs[g * 2 + 1], ah, kl + 2);
            }
        }

        // ---- alibi + causal mask ----
        const bool domask = (kb * 64 + 63 > qb * 128 + wq);
#pragma unroll
        for (int nt = 0; nt < 8; nt++) {
            const int kcol = kb * 64 + nt * 8 + tq * 2;
            const float2 av = *(const float2*)(alrow + kcol);
            cs[nt][0] += av.x; cs[nt][1] += av.y;
            cs[nt][2] += av.x; cs[nt][3] += av.y;
            if (domask) {
                if (kcol > q0)     cs[nt][0] = -1e30f;
                if (kcol + 1 > q0) cs[nt][1] = -1e30f;
                if (kcol > q1)     cs[nt][2] = -1e30f;
                if (kcol + 1 > q1) cs[nt][3] = -1e30f;
            }
        }

        // ---- online softmax (2 rows per lane); cs becomes fp32 P ----
        float mx0 = -1e30f, mx1 = -1e30f;
#pragma unroll
        for (int nt = 0; nt < 8; nt++) {
            mx0 = fmaxf(mx0, fmaxf(cs[nt][0], cs[nt][1]));
            mx1 = fmaxf(mx1, fmaxf(cs[nt][2], cs[nt][3]));
        }
        mx0 = fmaxf(mx0, __shfl_xor_sync(0xffffffffu, mx0, 1));
        mx0 = fmaxf(mx0, __shfl_xor_sync(0xffffffffu, mx0, 2));
        mx1 = fmaxf(mx1, __shfl_xor_sync(0xffffffffu, mx1, 1));
        mx1 = fmaxf(mx1, __shfl_xor_sync(0xffffffffu, mx1, 2));
        const float mn0 = fmaxf(m0, mx0);
        const float mn1 = fmaxf(m1, mx1);
        const float a0 = __expf(m0 - mn0);
        const float a1 = __expf(m1 - mn1);
        m0 = mn0; m1 = mn1;
        l0 *= a0; l1 *= a1;
#pragma unroll
        for (int nt = 0; nt < 16; nt++) {
            acc[nt][0] *= a0; acc[nt][1] *= a0;
            acc[nt][2] *= a1; acc[nt][3] *= a1;
        }

        float ps0 = 0.0f, ps1 = 0.0f;
#pragma unroll
        for (int nt = 0; nt < 8; nt++) {
            cs[nt][0] = __expf(cs[nt][0] - mn0);
            cs[nt][1] = __expf(cs[nt][1] - mn0);
            cs[nt][2] = __expf(cs[nt][2] - mn1);
            cs[nt][3] = __expf(cs[nt][3] - mn1);
            ps0 += cs[nt][0] + cs[nt][1];
            ps1 += cs[nt][2] + cs[nt][3];
        }
        ps0 += __shfl_xor_sync(0xffffffffu, ps0, 1);
        ps0 += __shfl_xor_sync(0xffffffffu, ps0, 2);
        ps1 += __shfl_xor_sync(0xffffffffu, ps1, 1);
        ps1 += __shfl_xor_sync(0xffffffffu, ps1, 2);
        l0 += ps0; l1 += ps1;

        // ---- P @ V (compensated: Phi.Vhi + Plo.Vhi + Phi.Vlo) ----
        const int vg = lane >> 3, vr = lane & 7;
#pragma unroll
        for (int ks2 = 0; ks2 < 4; ks2++) {
            uint32_t pahi[4], palo[4];
#pragma unroll
            for (int t = 0; t < 2; t++) {
                const int nt = 2 * ks2 + t;
                const __nv_bfloat16 h0 = __float2bfloat16(cs[nt][0]);
                const __nv_bfloat16 h1 = __float2bfloat16(cs[nt][1]);
                const __nv_bfloat16 h2 = __float2bfloat16(cs[nt][2]);
                const __nv_bfloat16 h3 = __float2bfloat16(cs[nt][3]);
                pahi[2 * t]     = pack_bf16(h0, h1);
                pahi[2 * t + 1] = pack_bf16(h2, h3);
                palo[2 * t]     = pack_bf16(__float2bfloat16(cs[nt][0] - __bfloat162float(h0)),
                                            __float2bfloat16(cs[nt][1] - __bfloat162float(h1)));
                palo[2 * t + 1] = pack_bf16(__float2bfloat16(cs[nt][2] - __bfloat162float(h2)),
                                            __float2bfloat16(cs[nt][3] - __bfloat162float(h3)));
            }
            const uint32_t vrow = (ks2 * 16 + (vg & 1) * 8 + vr) * ATROW + (vg >> 1) * 16;
#pragma unroll
            for (int dg = 0; dg < 8; dg++) {
                uint32_t th[4], tl[4];
                ldsm4t(th, kbuf + SV_HI + vrow + dg * 32);
                ldsm4t(tl, kbuf + SV_LO + vrow + dg * 32);
                mma16816(acc[dg * 2], pahi, th);
                mma16816(acc[dg * 2], palo, th);
                mma16816(acc[dg * 2], pahi, tl);
                mma16816(acc[dg * 2 + 1], pahi, th + 2);
                mma16816(acc[dg * 2 + 1], palo, th + 2);
                mma16816(acc[dg * 2 + 1], pahi, tl + 2);
            }
        }
        __syncthreads();
    }

    // ---- epilogue: ctx/l -> bf16 hi/lo directly into g_C2 ----
    const float il0 = 1.0f / l0;
    const float il1 = 1.0f / l1;
    const size_t r0 = ((size_t)b_ * SS + q0) * K2 + nh * 128;
    const size_t r1 = ((size_t)b_ * SS + q1) * K2 + nh * 128;
#pragma unroll
    for (int nt = 0; nt < 16; nt++) {
        const int d = nt * 8 + tq * 2;
        const float f0 = acc[nt][0] * il0, f1 = acc[nt][1] * il0;
        const float f2 = acc[nt][2] * il1, f3 = acc[nt][3] * il1;
        const __nv_bfloat16 h0 = __float2bfloat16(f0), h1 = __float2bfloat16(f1);
        const __nv_bfloat16 h2 = __float2bfloat16(f2), h3 = __float2bfloat16(f3);
        *(uint32_t*)(g_C2 + r0 + d) = pack_bf16(h0, h1);
        *(uint32_t*)(g_C2 + r1 + d) = pack_bf16(h2, h3);
        const __nv_bfloat16 e0 = __float2bfloat16(f0 - __bfloat162float(h0));
        const __nv_bfloat16 e1 = __float2bfloat16(f1 - __bfloat162float(h1));
        const __nv_bfloat16 e2 = __float2bfloat16(f2 - __bfloat162float(h2));
        const __nv_bfloat16 e3 = __float2bfloat16(f3 - __bfloat162float(h3));
        *(uint32_t*)(g_C2 + r0 + 4096 + d) = pack_bf16(e0, e1);
        *(uint32_t*)(g_C2 + r1 + 4096 + d) = pack_bf16(e2, e3);
    }
}

// ====================================================================
extern "C" void kernel_launch(void* const* d_in, const int* in_sizes, int n_in,
                              void* d_out, int out_size)
{
    (void)in_sizes; (void)n_in; (void)out_size;
    const float* hidden   = (const float*)d_in[0];
    const float* residual = (const float*)d_in[1];
    const float* alibi    = (const float*)d_in[2];
    // d_in[3] = attention_mask (causal; handled analytically)
    const float* W_qkv    = (const float*)d_in[4];
    const float* b_qkv    = (const float*)d_in[5];
    const float* W_dense  = (const float*)d_in[6];
    const float* b_dense  = (const float*)d_in[7];
    float* out = (float*)d_out;

    cudaFuncSetAttribute(hgemm_kernel<0>, cudaFuncAttributeMaxDynamicSharedMemorySize, GSM_TOTAL);
    cudaFuncSetAttribute(hgemm_kernel<1>, cudaFuncAttributeMaxDynamicSharedMemorySize, GSM_TOTAL);
    cudaFuncSetAttribute(attn_kernel, cudaFuncAttributeMaxDynamicSharedMemorySize, ATT_SMEM);

    convert_kernel<0><<<16384, 256>>>(hidden);    // hidden  -> A2 [hi|lo]
    convert_kernel<1><<<49152, 256>>>(W_qkv);     // W_qkv   -> W2
    convert_kernel<2><<<16384, 256>>>(W_dense);   // W_dense -> Wd2
    hgemm_kernel<0><<<1536, 256, GSM_TOTAL>>>(b_qkv, nullptr, nullptr);     // QKV
    attn_kernel<<<dim3(16, 64), 256, ATT_SMEM>>>(alibi);                    // flash attn (TC)
    hgemm_kernel<1><<<512, 256, GSM_TOTAL>>>(b_dense, residual, out);       // dense
}

// round 8
// speedup vs baseline: 1.4332x; 1.4332x over previous
#include <cuda_runtime.h>
#include <cuda_bf16.h>
#include <cstdint>

#define SS 2048
#define HH 4096
#define NHH 32
#define HDD 128
#define K2 8192
#define INV_NORM 0.088388347648318447f   // 1/sqrt(128)

// ---------------- scratch (__device__ globals; no allocs allowed) ----------------
__device__ __nv_bfloat16 g_qhi[16777216];   // [B,NH,S,HD] (pre-scaled by INV_NORM)
__device__ __nv_bfloat16 g_qlo[16777216];
__device__ __nv_bfloat16 g_khi[16777216];
__device__ __nv_bfloat16 g_klo[16777216];
__device__ __nv_bfloat16 g_vhi[16777216];
__device__ __nv_bfloat16 g_vlo[16777216];
__device__ __nv_bfloat16 g_A2[(size_t)4096 * K2];    // hidden  [hi|lo]
__device__ __nv_bfloat16 g_W2[(size_t)12288 * K2];   // W_qkv   [hi|lo]
__device__ __nv_bfloat16 g_Wd2[(size_t)4096 * K2];   // W_dense [hi|lo]
__device__ __nv_bfloat16 g_C2[(size_t)4096 * K2];    // ctx     [hi|lo]

// ---------------- PTX helpers ----------------
__device__ __forceinline__ uint32_t smem_u32(const void* p) {
    uint32_t a;
    asm("{ .reg .u64 t; cvta.to.shared.u64 t, %1; cvt.u32.u64 %0, t; }" : "=r"(a) : "l"(p));
    return a;
}
#define CP_ASYNC16(dst, src) \
    asm volatile("cp.async.cg.shared.global [%0], [%1], 16;" :: "r"(dst), "l"(src))
#define CP_COMMIT() asm volatile("cp.async.commit_group;" ::: "memory")
#define CP_WAIT1()  asm volatile("cp.async.wait_group 1;" ::: "memory")
#define CP_WAIT0()  asm volatile("cp.async.wait_group 0;" ::: "memory")

__device__ __forceinline__ void ldsm4(uint32_t* r, uint32_t addr) {
    asm volatile("ldmatrix.sync.aligned.m8n8.x4.shared.b16 {%0,%1,%2,%3}, [%4];"
        : "=r"(r[0]), "=r"(r[1]), "=r"(r[2]), "=r"(r[3]) : "r"(addr));
}
__device__ __forceinline__ void ldsm4t(uint32_t* r, uint32_t addr) {
    asm volatile("ldmatrix.sync.aligned.m8n8.x4.trans.shared.b16 {%0,%1,%2,%3}, [%4];"
        : "=r"(r[0]), "=r"(r[1]), "=r"(r[2]), "=r"(r[3]) : "r"(addr));
}
__device__ __forceinline__ void mma16816(float* c, const uint32_t* a, const uint32_t* b) {
    asm volatile(
        "mma.sync.aligned.m16n8k16.row.col.f32.bf16.bf16.f32 "
        "{%0,%1,%2,%3}, {%4,%5,%6,%7}, {%8,%9}, {%0,%1,%2,%3};"
        : "+f"(c[0]), "+f"(c[1]), "+f"(c[2]), "+f"(c[3])
        : "r"(a[0]), "r"(a[1]), "r"(a[2]), "r"(a[3]), "r"(b[0]), "r"(b[1]));
}
__device__ __forceinline__ uint32_t pack_bf16(__nv_bfloat16 a, __nv_bfloat16 b) {
    return (uint32_t)__bfloat16_as_ushort(a) | ((uint32_t)__bfloat16_as_ushort(b) << 16);
}

// ====================================================================
// fp32 [R][4096] -> bf16 [R][8192] as [hi | lo]
// ====================================================================
template<int WHICH>
__global__ void convert_kernel(const float* __restrict__ src) {
    size_t i = (size_t)blockIdx.x * 256 + threadIdx.x;  // one float4 per thread
    size_t r = i >> 10;
    int c = (int)(i & 1023) * 4;
    float4 v = *(const float4*)(src + (r << 12) + c);
    float f[4] = {v.x, v.y, v.z, v.w};
    unsigned short h[4], l[4];
#pragma unroll
    for (int j = 0; j < 4; j++) {
        __nv_bfloat16 hb = __float2bfloat16(f[j]);
        __nv_bfloat16 lb = __float2bfloat16(f[j] - __bfloat162float(hb));
        h[j] = __bfloat16_as_ushort(hb);
        l[j] = __bfloat16_as_ushort(lb);
    }
    uint2 hp = make_uint2((uint32_t)h[0] | ((uint32_t)h[1] << 16),
                          (uint32_t)h[2] | ((uint32_t)h[3] << 16));
    uint2 lp = make_uint2((uint32_t)l[0] | ((uint32_t)l[1] << 16),
                          (uint32_t)l[2] | ((uint32_t)l[3] << 16));
    __nv_bfloat16* dst = (WHICH == 0) ? g_A2 : (WHICH == 1) ? g_W2 : g_Wd2;
    __nv_bfloat16* base = dst + r * K2 + c;
    *(uint2*)(base) = hp;
    *(uint2*)(base + 4096) = lp;
}

// ====================================================================
// mma.sync bf16 GEMM, 3-term compensation via chunk remap.
// Tile 128x128, warp 64x32, BK=64, **3 stages, 1 sync/chunk**, 2 CTAs/SM.
//   c <  64 : hi.hi  (ak=c,     wk=c)
//   64..127 : lo.hi  (ak=c,     wk=c-64)
//   128..191: hi.lo  (ak=c-128, wk=c-64)
// MODE 0: scatter (+bias) to bf16 q/k/v hi+lo.  MODE 1: out+=bias+residual.
// ====================================================================
#define ROWB 144
#define TILEB (128 * ROWB)           // 18432 (A or B tile)
#define STG (2 * TILEB)              // 36864 per stage {A,B}
#define GSM_TOTAL (3 * STG)          // 110592
#define NCH 192

__device__ __forceinline__ int ak_of(int c) { return c & 127; }
__device__ __forceinline__ int wk_of(int c) { return (c < 64) ? c : c - 64; }

__device__ __forceinline__ void load_chunk(uint32_t sbuf,
    const __nv_bfloat16* Abase, const __nv_bfloat16* Wbase,
    int ak, int wk, int tid)
{
    const int row = tid >> 1;
    const int half = tid & 1;
    const __nv_bfloat16* asrc = Abase + (size_t)row * K2 + ak * 64 + half * 32;
    const uint32_t adst = sbuf + row * ROWB + half * 64;
#pragma unroll
    for (int i = 0; i < 4; i++) CP_ASYNC16(adst + i * 16, asrc + i * 8);
    const __nv_bfloat16* wsrc = Wbase + (size_t)row * K2 + wk * 64 + half * 32;
    const uint32_t wdst = sbuf + TILEB + row * ROWB + half * 64;
#pragma unroll
    for (int i = 0; i < 4; i++) CP_ASYNC16(wdst + i * 16, wsrc + i * 8);
}

template<int MODE>
__global__ __launch_bounds__(256, 2) void hgemm_kernel(
    const float* __restrict__ bias, const float* __restrict__ residual,
    float* __restrict__ out)
{
    extern __shared__ char smem[];
    const uint32_t sb = smem_u32(smem);
    const int tid = threadIdx.x;
    const int wid = tid >> 5;
    const int lane = tid & 31;
    const int wm = (wid >> 2) * 64;
    const int wn = (wid & 3) * 32;

    const int id = blockIdx.x;
    const int g = id >> 7;
    const int inner = id & 127;
    const int mg = g & 1;
    const int ng = g >> 1;
    const int bm = (mg * 16 + (inner & 15)) * 128;
    const int bn = (ng * 8 + (inner >> 4)) * 128;

    const __nv_bfloat16* Abase = ((MODE == 0) ? g_A2 : g_C2) + (size_t)bm * K2;
    const __nv_bfloat16* Wbase = ((MODE == 0) ? g_W2 : g_Wd2) + (size_t)bn * K2;

    float acc[4][4][4];
#pragma unroll
    for (int mt = 0; mt < 4; mt++)
#pragma unroll
        for (int nt = 0; nt < 4; nt++)
#pragma unroll
            for (int r = 0; r < 4; r++) acc[mt][nt][r] = 0.0f;

    // prologue: stages 0,1
    load_chunk(sb + 0 * STG, Abase, Wbase, ak_of(0), wk_of(0), tid); CP_COMMIT();
    load_chunk(sb + 1 * STG, Abase, Wbase, ak_of(1), wk_of(1), tid); CP_COMMIT();

    int s_cur = 0, s_nxt = 2;    // slot of chunk c; slot of chunk c+2
#pragma unroll 1
    for (int c = 0; c < NCH; c++) {
        if (c == NCH - 1) { CP_WAIT0(); } else { CP_WAIT1(); }
        __syncthreads();          // all warps done computing chunk c-1 -> slot s_nxt free
        const int cn = c + 2;
        if (cn < NCH) {
            load_chunk(sb + s_nxt * STG, Abase, Wbase, ak_of(cn), wk_of(cn), tid);
            CP_COMMIT();
        }

        const uint32_t abuf = sb + s_cur * STG;
        const uint32_t bbuf = abuf + TILEB;
#pragma unroll
        for (int ks = 0; ks < 4; ks++) {
            uint32_t afr[4][4], bfr[2][4];
#pragma unroll
            for (int mt = 0; mt < 4; mt++) {
                const uint32_t addr = abuf +
                    (wm + mt * 16 + ((lane >> 3) & 1) * 8 + (lane & 7)) * ROWB +
                    ks * 32 + ((lane >> 4) & 1) * 16;
                ldsm4(afr[mt], addr);
            }
#pragma unroll
            for (int bi = 0; bi < 2; bi++) {
                const uint32_t addr = bbuf +
                    (wn + bi * 16 + ((lane >> 4) & 1) * 8 + (lane & 7)) * ROWB +
                    ks * 32 + ((lane >> 3) & 1) * 16;
                ldsm4(bfr[bi], addr);
            }
#pragma unroll
            for (int mt = 0; mt < 4; mt++)
#pragma unroll
                for (int nt = 0; nt < 4; nt++)
                    mma16816(acc[mt][nt], afr[mt], &bfr[nt >> 1][(nt & 1) * 2]);
        }
        s_cur = (s_cur == 2) ? 0 : s_cur + 1;
        s_nxt = (s_nxt == 2) ? 0 : s_nxt + 1;
    }

    // ---------------- epilogue ----------------
    const int gq = lane >> 2;
    const int tq = lane & 3;
    if (MODE == 0) {
        const int sec = (bn >> 7) % 3;       // 0=q,1=k,2=v
        const int nh = bn / 384;
        const float scale = (sec == 0) ? INV_NORM : 1.0f;
        __nv_bfloat16* dhi = (sec == 0) ? g_qhi : (sec == 1) ? g_khi : g_vhi;
        __nv_bfloat16* dlo = (sec == 0) ? g_qlo : (sec == 1) ? g_klo : g_vlo;
#pragma unroll
        for (int mt = 0; mt < 4; mt++) {
            const int m0 = bm + wm + mt * 16 + gq;
#pragma unroll
            for (int nt = 0; nt < 4; nt++) {
                const int d = wn + nt * 8 + tq * 2;
                const float2 bv = *(const float2*)(bias + bn + d);
#pragma unroll
                for (int half = 0; half < 2; half++) {
                    const int m = m0 + half * 8;
                    const int b_ = m >> 11, s_ = m & 2047;
                    const size_t idx = (((size_t)(b_ * NHH + nh) * SS + s_) << 7) + d;
                    float v0 = (acc[mt][nt][half * 2 + 0] + bv.x) * scale;
                    float v1 = (acc[mt][nt][half * 2 + 1] + bv.y) * scale;
                    __nv_bfloat16 h0 = __float2bfloat16(v0);
                    __nv_bfloat16 h1 = __float2bfloat16(v1);
                    __nv_bfloat16 l0 = __float2bfloat16(v0 - __bfloat162float(h0));
                    __nv_bfloat16 l1 = __float2bfloat16(v1 - __bfloat162float(h1));
                    *(uint32_t*)(dhi + idx) = pack_bf16(h0, h1);
                    *(uint32_t*)(dlo + idx) = pack_bf16(l0, l1);
                }
            }
        }
    } else {
#pragma unroll
        for (int mt = 0; mt < 4; mt++) {
            const int m0 = bm + wm + mt * 16 + gq;
#pragma unroll
            for (int nt = 0; nt < 4; nt++) {
                const int n0 = bn + wn + nt * 8 + tq * 2;
                const float2 bv = *(const float2*)(bias + n0);
                {
                    const size_t i0 = (size_t)m0 * HH + n0;
                    const float2 rv = *(const float2*)(residual + i0);
                    *(float2*)(out + i0) = make_float2(acc[mt][nt][0] + bv.x + rv.x,
                                                       acc[mt][nt][1] + bv.y + rv.y);
                }
                {
                    const size_t i1 = (size_t)(m0 + 8) * HH + n0;
                    const float2 rv = *(const float2*)(residual + i1);
                    *(float2*)(out + i1) = make_float2(acc[mt][nt][2] + bv.x + rv.x,
                                                       acc[mt][nt][3] + bv.y + rv.y);
                }
            }
        }
    }
}

// ====================================================================
// Tensor-core causal flash attention with ALiBi — fully compensated.
// (unchanged from R6 — passing at rel_err 4.2e-5)
// ====================================================================
#define ATROW 272                       // 128 bf16 + 8 pad = 272 bytes
#define SQ_HI 0
#define SQ_LO (128 * ATROW)             // 34816
#define SBUF0 (2 * 128 * ATROW)         // 69632
#define SK_HI 0
#define SK_LO (64 * ATROW)
#define SV_HI (2 * 64 * ATROW)
#define SV_LO (3 * 64 * ATROW)
#define SBUF_SZ (4 * 64 * ATROW)        // 69632
#define ATT_SMEM (SBUF0 + 2 * SBUF_SZ)  // 208896

__device__ __forceinline__ void attn_load_kv(uint32_t sbuf, int bh, int kb, int tid)
{
    const int row = tid >> 2;           // 0..63
    const int off = (tid & 3) * 64;     // byte offset
    const size_t gidx = ((size_t)bh * SS + (size_t)kb * 64 + row) * HDD + (off >> 1);
    const uint32_t dbase = sbuf + row * ATROW + off;
#pragma unroll
    for (int i = 0; i < 4; i++) CP_ASYNC16(dbase + SK_HI + i * 16, g_khi + gidx + i * 8);
#pragma unroll
    for (int i = 0; i < 4; i++) CP_ASYNC16(dbase + SK_LO + i * 16, g_klo + gidx + i * 8);
#pragma unroll
    for (int i = 0; i < 4; i++) CP_ASYNC16(dbase + SV_HI + i * 16, g_vhi + gidx + i * 8);
#pragma unroll
    for (int i = 0; i < 4; i++) CP_ASYNC16(dbase + SV_LO + i * 16, g_vlo + gidx + i * 8);
}

__global__ __launch_bounds__(256) void attn_kernel(const float* __restrict__ alibi)
{
    extern __shared__ char smem[];
    const uint32_t sb = smem_u32(smem);
    const int tid = threadIdx.x;
    const int lane = tid & 31;
    const int wid = tid >> 5;
    const int wq = wid * 16;
    const int qb = (int)gridDim.x - 1 - (int)blockIdx.x;   // heavy CTAs first
    const int bh = blockIdx.y;
    const int b_ = bh >> 5;
    const int nh = bh & 31;

    const float* alrow = alibi + (size_t)bh * SS;

    // load Q tile (hi+lo), 128 rows x 256B
    {
        const int row = tid >> 1;
        const int off = (tid & 1) * 128;
        const size_t gidx = ((size_t)bh * SS + (size_t)qb * 128 + row) * HDD + (off >> 1);
        const uint32_t dq = sb + row * ATROW + off;
#pragma unroll
        for (int i = 0; i < 8; i++) CP_ASYNC16(dq + SQ_HI + i * 16, g_qhi + gidx + i * 8);
#pragma unroll
        for (int i = 0; i < 8; i++) CP_ASYNC16(dq + SQ_LO + i * 16, g_qlo + gidx + i * 8);
    }
    attn_load_kv(sb + SBUF0, bh, 0, tid);
    CP_COMMIT();

    const int kbmax = 2 * qb + 1;
    float m0 = -1e30f, m1 = -1e30f, l0 = 0.0f, l1 = 0.0f;
    float acc[16][4];
#pragma unroll
    for (int nt = 0; nt < 16; nt++)
#pragma unroll
        for (int r = 0; r < 4; r++) acc[nt][r] = 0.0f;

    const int gq = lane >> 2, tq = lane & 3;
    const int q0 = qb * 128 + wq + gq;
    const int q1 = q0 + 8;

#pragma unroll 1
    for (int kb = 0; kb <= kbmax; kb++) {
        if (kb < kbmax) {
            attn_load_kv(sb + SBUF0 + ((kb + 1) & 1) * SBUF_SZ, bh, kb + 1, tid);
            CP_COMMIT();
            CP_WAIT1();
        } else {
            CP_WAIT0();
        }
        __syncthreads();

        const uint32_t kbuf = sb + SBUF0 + (kb & 1) * SBUF_SZ;

        // ---- QK^T (compensated) ----
        float cs[8][4];
#pragma unroll
        for (int nt = 0; nt < 8; nt++)
#pragma unroll
            for (int r = 0; r < 4; r++) cs[nt][r] = 0.0f;

#pragma unroll
        for (int ks = 0; ks < 8; ks++) {
            uint32_t ah[4], alr[4];
            const uint32_t aaddr = sb +
                (wq + ((lane >> 3) & 1) * 8 + (lane & 7)) * ATROW +
                ks * 32 + ((lane >> 4) & 1) * 16;
            ldsm4(ah, aaddr + SQ_HI);
            ldsm4(alr, aaddr + SQ_LO);
#pragma unroll
            for (int g = 0; g < 4; g++) {
                uint32_t kh[4], kl[4];
                const uint32_t baddr = kbuf +
                    (g * 16 + ((lane >> 4) & 1) * 8 + (lane & 7)) * ATROW +
                    ks * 32 + ((lane >> 3) & 1) * 16;
                ldsm4(kh, baddr + SK_HI);
                ldsm4(kl, baddr + SK_LO);
                mma16816(cs[g * 2], ah, kh);
                mma16816(cs[g * 2], alr, kh);
                mma16816(cs[g * 2], ah, kl);
                mma16816(cs[g * 2 + 1], ah, kh + 2);
                mma16816(cs[g * 2 + 1], alr, kh + 2);
                mma16816(cs[g * 2 + 1], ah, kl + 2);
            }
        }

        // ---- alibi + causal mask ----
        const bool domask = (kb * 64 + 63 > qb * 128 + wq);
#pragma unroll
        for (int nt = 0; nt < 8; nt++) {
            const int kcol = kb * 64 + nt * 8 + tq * 2;
            const float2 av = *(const float2*)(alrow + kcol);
            cs[nt][0] += av.x; cs[nt][1] += av.y;
            cs[nt][2] += av.x; cs[nt][3] += av.y;
            if (domask) {
                if (kcol > q0)     cs[nt][0] = -1e30f;
                if (kcol + 1 > q0) cs[nt][1] = -1e30f;
                if (kcol > q1)     cs[nt][2] = -1e30f;
                if (kcol + 1 > q1) cs[nt][3] = -1e30f;
            }
        }

        // ---- online softmax (2 rows per lane); cs becomes fp32 P ----
        float mx0 = -1e30f, mx1 = -1e30f;
#pragma unroll
        for (int nt = 0; nt < 8; nt++) {
            mx0 = fmaxf(mx0, fmaxf(cs[nt][0], cs[nt][1]));
            mx1 = fmaxf(mx1, fmaxf(cs[nt][2], cs[nt][3]));
        }
        mx0 = fmaxf(mx0, __shfl_xor_sync(0xffffffffu, mx0, 1));
        mx0 = fmaxf(mx0, __shfl_xor_sync(0xffffffffu, mx0, 2));
        mx1 = fmaxf(mx1, __shfl_xor_sync(0xffffffffu, mx1, 1));
        mx1 = fmaxf(mx1, __shfl_xor_sync(0xffffffffu, mx1, 2));
        const float mn0 = fmaxf(m0, mx0);
        const float mn1 = fmaxf(m1, mx1);
        const float a0 = __expf(m0 - mn0);
        const float a1 = __expf(m1 - mn1);
        m0 = mn0; m1 = mn1;
        l0 *= a0; l1 *= a1;
#pragma unroll
        for (int nt = 0; nt < 16; nt++) {
            acc[nt][0] *= a0; acc[nt][1] *= a0;
            acc[nt][2] *= a1; acc[nt][3] *= a1;
        }

        float ps0 = 0.0f, ps1 = 0.0f;
#pragma unroll
        for (int nt = 0; nt < 8; nt++) {
            cs[nt][0] = __expf(cs[nt][0] - mn0);
            cs[nt][1] = __expf(cs[nt][1] - mn0);
            cs[nt][2] = __expf(cs[nt][2] - mn1);
            cs[nt][3] = __expf(cs[nt][3] - mn1);
            ps0 += cs[nt][0] + cs[nt][1];
            ps1 += cs[nt][2] + cs[nt][3];
        }
        ps0 += __shfl_xor_sync(0xffffffffu, ps0, 1);
        ps0 += __shfl_xor_sync(0xffffffffu, ps0, 2);
        ps1 += __shfl_xor_sync(0xffffffffu, ps1, 1);
        ps1 += __shfl_xor_sync(0xffffffffu, ps1, 2);
        l0 += ps0; l1 += ps1;

        // ---- P @ V (compensated: Phi.Vhi + Plo.Vhi + Phi.Vlo) ----
        const int vg = lane >> 3, vr = lane & 7;
#pragma unroll
        for (int ks2 = 0; ks2 < 4; ks2++) {
            uint32_t pahi[4], palo[4];
#pragma unroll
            for (int t = 0; t < 2; t++) {
                const int nt = 2 * ks2 + t;
                const __nv_bfloat16 h0 = __float2bfloat16(cs[nt][0]);
                const __nv_bfloat16 h1 = __float2bfloat16(cs[nt][1]);
                const __nv_bfloat16 h2 = __float2bfloat16(cs[nt][2]);
                const __nv_bfloat16 h3 = __float2bfloat16(cs[nt][3]);
                pahi[2 * t]     = pack_bf16(h0, h1);
                pahi[2 * t + 1] = pack_bf16(h2, h3);
                palo[2 * t]     = pack_bf16(__float2bfloat16(cs[nt][0] - __bfloat162float(h0)),
                                            __float2bfloat16(cs[nt][1] - __bfloat162float(h1)));
                palo[2 * t + 1] = pack_bf16(__float2bfloat16(cs[nt][2] - __bfloat162float(h2)),
                                            __float2bfloat16(cs[nt][3] - __bfloat162float(h3)));
            }
            const uint32_t vrow = (ks2 * 16 + (vg & 1) * 8 + vr) * ATROW + (vg >> 1) * 16;
#pragma unroll
            for (int dg = 0; dg < 8; dg++) {
                uint32_t th[4], tl[4];
                ldsm4t(th, kbuf + SV_HI + vrow + dg * 32);
                ldsm4t(tl, kbuf + SV_LO + vrow + dg * 32);
                mma16816(acc[dg * 2], pahi, th);
                mma16816(acc[dg * 2], palo, th);
                mma16816(acc[dg * 2], pahi, tl);
                mma16816(acc[dg * 2 + 1], pahi, th + 2);
                mma16816(acc[dg * 2 + 1], palo, th + 2);
                mma16816(acc[dg * 2 + 1], pahi, tl + 2);
            }
        }
        __syncthreads();
    }

    // ---- epilogue: ctx/l -> bf16 hi/lo directly into g_C2 ----
    const float il0 = 1.0f / l0;
    const float il1 = 1.0f / l1;
    const size_t r0 = ((size_t)b_ * SS + q0) * K2 + nh * 128;
    const size_t r1 = ((size_t)b_ * SS + q1) * K2 + nh * 128;
#pragma unroll
    for (int nt = 0; nt < 16; nt++) {
        const int d = nt * 8 + tq * 2;
        const float f0 = acc[nt][0] * il0, f1 = acc[nt][1] * il0;
        const float f2 = acc[nt][2] * il1, f3 = acc[nt][3] * il1;
        const __nv_bfloat16 h0 = __float2bfloat16(f0), h1 = __float2bfloat16(f1);
        const __nv_bfloat16 h2 = __float2bfloat16(f2), h3 = __float2bfloat16(f3);
        *(uint32_t*)(g_C2 + r0 + d) = pack_bf16(h0, h1);
        *(uint32_t*)(g_C2 + r1 + d) = pack_bf16(h2, h3);
        const __nv_bfloat16 e0 = __float2bfloat16(f0 - __bfloat162float(h0));
        const __nv_bfloat16 e1 = __float2bfloat16(f1 - __bfloat162float(h1));
        const __nv_bfloat16 e2 = __float2bfloat16(f2 - __bfloat162float(h2));
        const __nv_bfloat16 e3 = __float2bfloat16(f3 - __bfloat162float(h3));
        *(uint32_t*)(g_C2 + r0 + 4096 + d) = pack_bf16(e0, e1);
        *(uint32_t*)(g_C2 + r1 + 4096 + d) = pack_bf16(e2, e3);
    }
}

// ====================================================================
extern "C" void kernel_launch(void* const* d_in, const int* in_sizes, int n_in,
                              void* d_out, int out_size)
{
    (void)in_sizes; (void)n_in; (void)out_size;
    const float* hidden   = (const float*)d_in[0];
    const float* residual = (const float*)d_in[1];
    const float* alibi    = (const float*)d_in[2];
    // d_in[3] = attention_mask (causal; handled analytically)
    const float* W_qkv    = (const float*)d_in[4];
    const float* b_qkv    = (const float*)d_in[5];
    const float* W_dense  = (const float*)d_in[6];
    const float* b_dense  = (const float*)d_in[7];
    float* out = (float*)d_out;

    cudaFuncSetAttribute(hgemm_kernel<0>, cudaFuncAttributeMaxDynamicSharedMemorySize, GSM_TOTAL);
    cudaFuncSetAttribute(hgemm_kernel<1>, cudaFuncAttributeMaxDynamicSharedMemorySize, GSM_TOTAL);
    cudaFuncSetAttribute(attn_kernel, cudaFuncAttributeMaxDynamicSharedMemorySize, ATT_SMEM);

    convert_kernel<0><<<16384, 256>>>(hidden);    // hidden  -> A2 [hi|lo]
    convert_kernel<1><<<49152, 256>>>(W_qkv);     // W_qkv   -> W2
    convert_kernel<2><<<16384, 256>>>(W_dense);   // W_dense -> Wd2
    hgemm_kernel<0><<<3072, 256, GSM_TOTAL>>>(b_qkv, nullptr, nullptr);     // QKV
    attn_kernel<<<dim3(16, 64), 256, ATT_SMEM>>>(alibi);                    // flash attn (TC)
    hgemm_kernel<1><<<1024, 256, GSM_TOTAL>>>(b_dense, residual, out);      // dense
}

// round 13
// speedup vs baseline: 1.7268x; 1.2048x over previous
#include <cuda_runtime.h>
#include <cuda_bf16.h>
#include <cstdint>

#define SS 2048
#define HH 4096
#define NHH 32
#define HDD 128
#define K2 8192
#define INV_NORM 0.088388347648318447f   // 1/sqrt(128)

// ---------------- scratch (__device__ globals; no allocs allowed) ----------------
__device__ __nv_bfloat16 g_qhi[16777216];   // [B,NH,S,HD] (pre-scaled by INV_NORM)
__device__ __nv_bfloat16 g_qlo[16777216];
__device__ __nv_bfloat16 g_khi[16777216];
__device__ __nv_bfloat16 g_klo[16777216];
__device__ __nv_bfloat16 g_vhi[16777216];
__device__ __nv_bfloat16 g_vlo[16777216];
__device__ __nv_bfloat16 g_A2[(size_t)4096 * K2];    // hidden  [hi|lo]
__device__ __nv_bfloat16 g_W2[(size_t)12288 * K2];   // W_qkv   [hi|lo]
__device__ __nv_bfloat16 g_Wd2[(size_t)4096 * K2];   // W_dense [hi|lo]
__device__ __nv_bfloat16 g_C2[(size_t)4096 * K2];    // ctx     [hi|lo]

// ---------------- PTX helpers ----------------
__device__ __forceinline__ uint32_t smem_u32(const void* p) {
    uint32_t a;
    asm("{ .reg .u64 t; cvta.to.shared.u64 t, %1; cvt.u32.u64 %0, t; }" : "=r"(a) : "l"(p));
    return a;
}
#define CP_ASYNC16(dst, src) \
    asm volatile("cp.async.cg.shared.global [%0], [%1], 16;" :: "r"(dst), "l"(src))
#define CP_COMMIT() asm volatile("cp.async.commit_group;" ::: "memory")
#define CP_WAIT1()  asm volatile("cp.async.wait_group 1;" ::: "memory")
#define CP_WAIT0()  asm volatile("cp.async.wait_group 0;" ::: "memory")

__device__ __forceinline__ void ldsm4(uint32_t* r, uint32_t addr) {
    asm volatile("ldmatrix.sync.aligned.m8n8.x4.shared.b16 {%0,%1,%2,%3}, [%4];"
        : "=r"(r[0]), "=r"(r[1]), "=r"(r[2]), "=r"(r[3]) : "r"(addr));
}
__device__ __forceinline__ void ldsm4t(uint32_t* r, uint32_t addr) {
    asm volatile("ldmatrix.sync.aligned.m8n8.x4.trans.shared.b16 {%0,%1,%2,%3}, [%4];"
        : "=r"(r[0]), "=r"(r[1]), "=r"(r[2]), "=r"(r[3]) : "r"(addr));
}
__device__ __forceinline__ void mma16816(float* c, const uint32_t* a, const uint32_t* b) {
    asm volatile(
        "mma.sync.aligned.m16n8k16.row.col.f32.bf16.bf16.f32 "
        "{%0,%1,%2,%3}, {%4,%5,%6,%7}, {%8,%9}, {%0,%1,%2,%3};"
        : "+f"(c[0]), "+f"(c[1]), "+f"(c[2]), "+f"(c[3])
        : "r"(a[0]), "r"(a[1]), "r"(a[2]), "r"(a[3]), "r"(b[0]), "r"(b[1]));
}
__device__ __forceinline__ uint32_t pack_bf16(__nv_bfloat16 a, __nv_bfloat16 b) {
    return (uint32_t)__bfloat16_as_ushort(a) | ((uint32_t)__bfloat16_as_ushort(b) << 16);
}

// ====================================================================
// fp32 [R][4096] -> bf16 [R][8192] as [hi | lo]
// ====================================================================
template<int WHICH>
__global__ void convert_kernel(const float* __restrict__ src) {
    size_t i = (size_t)blockIdx.x * 256 + threadIdx.x;  // one float4 per thread
    size_t r = i >> 10;
    int c = (int)(i & 1023) * 4;
    float4 v = *(const float4*)(src + (r << 12) + c);
    float f[4] = {v.x, v.y, v.z, v.w};
    unsigned short h[4], l[4];
#pragma unroll
    for (int j = 0; j < 4; j++) {
        __nv_bfloat16 hb = __float2bfloat16(f[j]);
        __nv_bfloat16 lb = __float2bfloat16(f[j] - __bfloat162float(hb));
        h[j] = __bfloat16_as_ushort(hb);
        l[j] = __bfloat16_as_ushort(lb);
    }
    uint2 hp = make_uint2((uint32_t)h[0] | ((uint32_t)h[1] << 16),
                          (uint32_t)h[2] | ((uint32_t)h[3] << 16));
    uint2 lp = make_uint2((uint32_t)l[0] | ((uint32_t)l[1] << 16),
                          (uint32_t)l[2] | ((uint32_t)l[3] << 16));
    __nv_bfloat16* dst = (WHICH == 0) ? g_A2 : (WHICH == 1) ? g_W2 : g_Wd2;
    __nv_bfloat16* base = dst + r * K2 + c;
    *(uint2*)(base) = hp;
    *(uint2*)(base + 4096) = lp;
}

// ---- shared chunk-remap for the 3-term compensation (BK=64, NCH=192) ----
#define NCH 192
__device__ __forceinline__ int ak_of(int c) { return c & 127; }
__device__ __forceinline__ int wk_of(int c) { return (c < 64) ? c : c - 64; }

// ====================================================================
// WIDE QKV GEMM: tile 128x256, 512 threads (16 warps, warp 64x32),
// BK=64, 3 stages, single barrier per chunk, 1 CTA/SM.
// Shares one B tile across all 16 warps -> 33% less L2 traffic/MAC.
// Epilogue: scatter (+bias) to bf16 q/k/v hi+lo.
// ====================================================================
#define WROWB 144
#define WA_BYTES (128 * WROWB)          // 18432
#define WB_BYTES (256 * WROWB)          // 36864
#define WSTG (WA_BYTES + WB_BYTES)      // 55296
#define WSM_TOTAL (3 * WSTG)            // 165888

__device__ __forceinline__ void load_chunk_w(uint32_t sbuf,
    const __nv_bfloat16* Abase, const __nv_bfloat16* Wbase,
    int ak, int wk, int tid)
{
#pragma unroll
    for (int i = 0; i < 6; i++) {
        const int idx = tid + i * 512;
        const int row = idx >> 3;       // 0..383
        const int seg = idx & 7;        // 16B segment
        if (row < 128) {
            CP_ASYNC16(sbuf + row * WROWB + seg * 16,
                       Abase + (size_t)row * K2 + ak * 64 + seg * 8);
        } else {
            CP_ASYNC16(sbuf + WA_BYTES + (row - 128) * WROWB + seg * 16,
                       Wbase + (size_t)(row - 128) * K2 + wk * 64 + seg * 8);
        }
    }
}

__global__ __launch_bounds__(512, 1) void hgemm_wide_kernel(const float* __restrict__ bias)
{
    extern __shared__ char smem[];
    const uint32_t sb = smem_u32(smem);
    const int tid = threadIdx.x;
    const int wid = tid >> 5;
    const int lane = tid & 31;
    const int wm = (wid >> 3) * 64;       // 2 m-groups of 64
    const int wn = (wid & 7) * 32;        // 8 n-groups of 32

    // raster: 2 M-groups of 16, N-major inside (48 N-tiles of 256)
    const int id = blockIdx.x;
    const int g = id / 768;
    const int inner = id - g * 768;
    const int bm = (g * 16 + (inner & 15)) * 128;
    const int bn = (inner >> 4) * 256;

    const __nv_bfloat16* Abase = g_A2 + (size_t)bm * K2;
    const __nv_bfloat16* Wbase = g_W2 + (size_t)bn * K2;

    float acc[4][4][4];
#pragma unroll
    for (int mt = 0; mt < 4; mt++)
#pragma unroll
        for (int nt = 0; nt < 4; nt++)
#pragma unroll
            for (int r = 0; r < 4; r++) acc[mt][nt][r] = 0.0f;

    load_chunk_w(sb + 0 * WSTG, Abase, Wbase, ak_of(0), wk_of(0), tid); CP_COMMIT();
    load_chunk_w(sb + 1 * WSTG, Abase, Wbase, ak_of(1), wk_of(1), tid); CP_COMMIT();

    int s_cur = 0, s_nxt = 2;
#pragma unroll 1
    for (int c = 0; c < NCH; c++) {
        if (c == NCH - 1) { CP_WAIT0(); } else { CP_WAIT1(); }
        __syncthreads();          // all warps done with chunk c-1 -> slot s_nxt free
        const int cn = c + 2;
        if (cn < NCH) {
            load_chunk_w(sb + s_nxt * WSTG, Abase, Wbase, ak_of(cn), wk_of(cn), tid);
            CP_COMMIT();
        }

        const uint32_t abuf = sb + s_cur * WSTG;
        const uint32_t bbuf = abuf + WA_BYTES;
#pragma unroll
        for (int ks = 0; ks < 4; ks++) {
            uint32_t afr[4][4], bfr[2][4];
#pragma unroll
            for (int mt = 0; mt < 4; mt++) {
                const uint32_t addr = abuf +
                    (wm + mt * 16 + ((lane >> 3) & 1) * 8 + (lane & 7)) * WROWB +
                    ks * 32 + ((lane >> 4) & 1) * 16;
                ldsm4(afr[mt], addr);
            }
#pragma unroll
            for (int bi = 0; bi < 2; bi++) {
                const uint32_t addr = bbuf +
                    (wn + bi * 16 + ((lane >> 4) & 1) * 8 + (lane & 7)) * WROWB +
                    ks * 32 + ((lane >> 3) & 1) * 16;
                ldsm4(bfr[bi], addr);
            }
#pragma unroll
            for (int mt = 0; mt < 4; mt++)
#pragma unroll
                for (int nt = 0; nt < 4; nt++)
                    mma16816(acc[mt][nt], afr[mt], &bfr[nt >> 1][(nt & 1) * 2]);
        }
        s_cur = (s_cur == 2) ? 0 : s_cur + 1;
        s_nxt = (s_nxt == 2) ? 0 : s_nxt + 1;
    }

    // ---------------- epilogue: scatter to q/k/v hi+lo ----------------
    const int gq = lane >> 2;
    const int tq = lane & 3;
    const int n0base = bn + wn;          // 32-aligned -> one section per warp
    const int sec = (n0base >> 7) % 3;   // 0=q,1=k,2=v
    const int nh = n0base / 384;
    const int dbase = n0base & 127;
    const float scale = (sec == 0) ? INV_NORM : 1.0f;
    __nv_bfloat16* dhi = (sec == 0) ? g_qhi : (sec == 1) ? g_khi : g_vhi;
    __nv_bfloat16* dlo = (sec == 0) ? g_qlo : (sec == 1) ? g_klo : g_vlo;
#pragma unroll
    for (int mt = 0; mt < 4; mt++) {
        const int m0 = bm + wm + mt * 16 + gq;
#pragma unroll
        for (int nt = 0; nt < 4; nt++) {
            const int d = dbase + nt * 8 + tq * 2;
            const float2 bv = *(const float2*)(bias + n0base + nt * 8 + tq * 2);
#pragma unroll
            for (int half = 0; half < 2; half++) {
                const int m = m0 + half * 8;
                const int b_ = m >> 11, s_ = m & 2047;
                const size_t idx = (((size_t)(b_ * NHH + nh) * SS + s_) << 7) + d;
                float v0 = (acc[mt][nt][half * 2 + 0] + bv.x) * scale;
                float v1 = (acc[mt][nt][half * 2 + 1] + bv.y) * scale;
                __nv_bfloat16 h0 = __float2bfloat16(v0);
                __nv_bfloat16 h1 = __float2bfloat16(v1);
                __nv_bfloat16 l0 = __float2bfloat16(v0 - __bfloat162float(h0));
                __nv_bfloat16 l1 = __float2bfloat16(v1 - __bfloat162float(h1));
                *(uint32_t*)(dhi + idx) = pack_bf16(h0, h1);
                *(uint32_t*)(dlo + idx) = pack_bf16(l0, l1);
            }
        }
    }
}

// ====================================================================
// Dense GEMM (proven R8 config): tile 128x128, warp 64x32, BK=64,
// 3 stages, 1 sync/chunk, 2 CTAs/SM. out = acc + bias + residual.
// ====================================================================
#define ROWB 144
#define TILEB (128 * ROWB)
#define STG (2 * TILEB)
#define GSM_TOTAL (3 * STG)          // 110592

__device__ __forceinline__ void load_chunk(uint32_t sbuf,
    const __nv_bfloat16* Abase, const __nv_bfloat16* Wbase,
    int ak, int wk, int tid)
{
    const int row = tid >> 1;
    const int half = tid & 1;
    const __nv_bfloat16* asrc = Abase + (size_t)row * K2 + ak * 64 + half * 32;
    const uint32_t adst = sbuf + row * ROWB + half * 64;
#pragma unroll
    for (int i = 0; i < 4; i++) CP_ASYNC16(adst + i * 16, asrc + i * 8);
    const __nv_bfloat16* wsrc = Wbase + (size_t)row * K2 + wk * 64 + half * 32;
    const uint32_t wdst = sbuf + TILEB + row * ROWB + half * 64;
#pragma unroll
    for (int i = 0; i < 4; i++) CP_ASYNC16(wdst + i * 16, wsrc + i * 8);
}

__global__ __launch_bounds__(256, 2) void hgemm_dense_kernel(
    const float* __restrict__ bias, const float* __restrict__ residual,
    float* __restrict__ out)
{
    extern __shared__ char smem[];
    const uint32_t sb = smem_u32(smem);
    const int tid = threadIdx.x;
    const int wid = tid >> 5;
    const int lane = tid & 31;
    const int wm = (wid >> 2) * 64;
    const int wn = (wid & 3) * 32;

    const int id = blockIdx.x;
    const int g = id >> 7;
    const int inner = id & 127;
    const int mg = g & 1;
    const int ng = g >> 1;
    const int bm = (mg * 16 + (inner & 15)) * 128;
    const int bn = (ng * 8 + (inner >> 4)) * 128;

    const __nv_bfloat16* Abase = g_C2 + (size_t)bm * K2;
    const __nv_bfloat16* Wbase = g_Wd2 + (size_t)bn * K2;

    float acc[4][4][4];
#pragma unroll
    for (int mt = 0; mt < 4; mt++)
#pragma unroll
        for (int nt = 0; nt < 4; nt++)
#pragma unroll
            for (int r = 0; r < 4; r++) acc[mt][nt][r] = 0.0f;

    load_chunk(sb + 0 * STG, Abase, Wbase, ak_of(0), wk_of(0), tid); CP_COMMIT();
    load_chunk(sb + 1 * STG, Abase, Wbase, ak_of(1), wk_of(1), tid); CP_COMMIT();

    int s_cur = 0, s_nxt = 2;
#pragma unroll 1
    for (int c = 0; c < NCH; c++) {
        if (c == NCH - 1) { CP_WAIT0(); } else { CP_WAIT1(); }
        __syncthreads();
        const int cn = c + 2;
        if (cn < NCH) {
            load_chunk(sb + s_nxt * STG, Abase, Wbase, ak_of(cn), wk_of(cn), tid);
            CP_COMMIT();
        }

        const uint32_t abuf = sb + s_cur * STG;
        const uint32_t bbuf = abuf + TILEB;
#pragma unroll
        for (int ks = 0; ks < 4; ks++) {
            uint32_t afr[4][4], bfr[2][4];
#pragma unroll
            for (int mt = 0; mt < 4; mt++) {
                const uint32_t addr = abuf +
                    (wm + mt * 16 + ((lane >> 3) & 1) * 8 + (lane & 7)) * ROWB +
                    ks * 32 + ((lane >> 4) & 1) * 16;
                ldsm4(afr[mt], addr);
            }
#pragma unroll
            for (int bi = 0; bi < 2; bi++) {
                const uint32_t addr = bbuf +
                    (wn + bi * 16 + ((lane >> 4) & 1) * 8 + (lane & 7)) * ROWB +
                    ks * 32 + ((lane >> 3) & 1) * 16;
                ldsm4(bfr[bi], addr);
            }
#pragma unroll
            for (int mt = 0; mt < 4; mt++)
#pragma unroll
                for (int nt = 0; nt < 4; nt++)
                    mma16816(acc[mt][nt], afr[mt], &bfr[nt >> 1][(nt & 1) * 2]);
        }
        s_cur = (s_cur == 2) ? 0 : s_cur + 1;
        s_nxt = (s_nxt == 2) ? 0 : s_nxt + 1;
    }

    const int gq = lane >> 2;
    const int tq = lane & 3;
#pragma unroll
    for (int mt = 0; mt < 4; mt++) {
        const int m0 = bm + wm + mt * 16 + gq;
#pragma unroll
        for (int nt = 0; nt < 4; nt++) {
            const int n0 = bn + wn + nt * 8 + tq * 2;
            const float2 bv = *(const float2*)(bias + n0);
            {
                const size_t i0 = (size_t)m0 * HH + n0;
                const float2 rv = *(const float2*)(residual + i0);
                *(float2*)(out + i0) = make_float2(acc[mt][nt][0] + bv.x + rv.x,
                                                   acc[mt][nt][1] + bv.y + rv.y);
            }
            {
                const size_t i1 = (size_t)(m0 + 8) * HH + n0;
                const float2 rv = *(const float2*)(residual + i1);
                *(float2*)(out + i1) = make_float2(acc[mt][nt][2] + bv.x + rv.x,
                                                   acc[mt][nt][3] + bv.y + rv.y);
            }
        }
    }
}

// ====================================================================
// Tensor-core causal flash attention with ALiBi — fully compensated.
// (unchanged from R6/R8 — passing at rel_err 4.2e-5)
// ====================================================================
#define ATROW 272                       // 128 bf16 + 8 pad = 272 bytes
#define SQ_HI 0
#define SQ_LO (128 * ATROW)             // 34816
#define SBUF0 (2 * 128 * ATROW)         // 69632
#define SK_HI 0
#define SK_LO (64 * ATROW)
#define SV_HI (2 * 64 * ATROW)
#define SV_LO (3 * 64 * ATROW)
#define SBUF_SZ (4 * 64 * ATROW)        // 69632
#define ATT_SMEM (SBUF0 + 2 * SBUF_SZ)  // 208896

__device__ __forceinline__ void attn_load_kv(uint32_t sbuf, int bh, int kb, int tid)
{
    const int row = tid >> 2;           // 0..63
    const int off = (tid & 3) * 64;     // byte offset
    const size_t gidx = ((size_t)bh * SS + (size_t)kb * 64 + row) * HDD + (off >> 1);
    const uint32_t dbase = sbuf + row * ATROW + off;
#pragma unroll
    for (int i = 0; i < 4; i++) CP_ASYNC16(dbase + SK_HI + i * 16, g_khi + gidx + i * 8);
#pragma unroll
    for (int i = 0; i < 4; i++) CP_ASYNC16(dbase + SK_LO + i * 16, g_klo + gidx + i * 8);
#pragma unroll
    for (int i = 0; i < 4; i++) CP_ASYNC16(dbase + SV_HI + i * 16, g_vhi + gidx + i * 8);
#pragma unroll
    for (int i = 0; i < 4; i++) CP_ASYNC16(dbase + SV_LO + i * 16, g_vlo + gidx + i * 8);
}

__global__ __launch_bounds__(256) void attn_kernel(const float* __restrict__ alibi)
{
    extern __shared__ char smem[];
    const uint32_t sb = smem_u32(smem);
    const int tid = threadIdx.x;
    const int lane = tid & 31;
    const int wid = tid >> 5;
    const int wq = wid * 16;
    const int qb = (int)gridDim.x - 1 - (int)blockIdx.x;   // heavy CTAs first
    const int bh = blockIdx.y;
    const int b_ = bh >> 5;
    const int nh = bh & 31;

    const float* alrow = alibi + (size_t)bh * SS;

    {
        const int row = tid >> 1;
        const int off = (tid & 1) * 128;
        const size_t gidx = ((size_t)bh * SS + (size_t)qb * 128 + row) * HDD + (off >> 1);
        const uint32_t dq = sb + row * ATROW + off;
#pragma unroll
        for (int i = 0; i < 8; i++) CP_ASYNC16(dq + SQ_HI + i * 16, g_qhi + gidx + i * 8);
#pragma unroll
        for (int i = 0; i < 8; i++) CP_ASYNC16(dq + SQ_LO + i * 16, g_qlo + gidx + i * 8);
    }
    attn_load_kv(sb + SBUF0, bh, 0, tid);
    CP_COMMIT();

    const int kbmax = 2 * qb + 1;
    float m0 = -1e30f, m1 = -1e30f, l0 = 0.0f, l1 = 0.0f;
    float acc[16][4];
#pragma unroll
    for (int nt = 0; nt < 16; nt++)
#pragma unroll
        for (int r = 0; r < 4; r++) acc[nt][r] = 0.0f;

    const int gq = lane >> 2, tq = lane & 3;
    const int q0 = qb * 128 + wq + gq;
    const int q1 = q0 + 8;

#pragma unroll 1
    for (int kb = 0; kb <= kbmax; kb++) {
        if (kb < kbmax) {
            attn_load_kv(sb + SBUF0 + ((kb + 1) & 1) * SBUF_SZ, bh, kb + 1, tid);
            CP_COMMIT();
            CP_WAIT1();
        } else {
            CP_WAIT0();
        }
        __syncthreads();

        const uint32_t kbuf = sb + SBUF0 + (kb & 1) * SBUF_SZ;

        float cs[8][4];
#pragma unroll
        for (int nt = 0; nt < 8; nt++)
#pragma unroll
            for (int r = 0; r < 4; r++) cs[nt][r] = 0.0f;

#pragma unroll
        for (int ks = 0; ks < 8; ks++) {
            uint32_t ah[4], alr[4];
            const uint32_t aaddr = sb +
                (wq + ((lane >> 3) & 1) * 8 + (lane & 7)) * ATROW +
                ks * 32 + ((lane >> 4) & 1) * 16;
            ldsm4(ah, aaddr + SQ_HI);
            ldsm4(alr, aaddr + SQ_LO);
#pragma unroll
            for (int g = 0; g < 4; g++) {
                uint32_t kh[4], kl[4];
                const uint32_t baddr = kbuf +
                    (g * 16 + ((lane >> 4) & 1) * 8 + (lane & 7)) * ATROW +
                    ks * 32 + ((lane >> 3) & 1) * 16;
                ldsm4(kh, baddr + SK_HI);
                ldsm4(kl, baddr + SK_LO);
                mma16816(cs[g * 2], ah, kh);
                mma16816(cs[g * 2], alr, kh);
                mma16816(cs[g * 2], ah, kl);
                mma16816(cs[g * 2 + 1], ah, kh + 2);
                mma16816(cs[g * 2 + 1], alr, kh + 2);
                mma16816(cs[g * 2 + 1], ah, kl + 2);
            }
        }

        const bool domask = (kb * 64 + 63 > qb * 128 + wq);
#pragma unroll
        for (int nt = 0; nt < 8; nt++) {
            const int kcol = kb * 64 + nt * 8 + tq * 2;
            const float2 av = *(const float2*)(alrow + kcol);
            cs[nt][0] += av.x; cs[nt][1] += av.y;
            cs[nt][2] += av.x; cs[nt][3] += av.y;
            if (domask) {
                if (kcol > q0)     cs[nt][0] = -1e30f;
                if (kcol + 1 > q0) cs[nt][1] = -1e30f;
                if (kcol > q1)     cs[nt][2] = -1e30f;
                if (kcol + 1 > q1) cs[nt][3] = -1e30f;
            }
        }

        float mx0 = -1e30f, mx1 = -1e30f;
#pragma unroll
        for (int nt = 0; nt < 8; nt++) {
            mx0 = fmaxf(mx0, fmaxf(cs[nt][0], cs[nt][1]));
            mx1 = fmaxf(mx1, fmaxf(cs[nt][2], cs[nt][3]));
        }
        mx0 = fmaxf(mx0, __shfl_xor_sync(0xffffffffu, mx0, 1));
        mx0 = fmaxf(mx0, __shfl_xor_sync(0xffffffffu, mx0, 2));
        mx1 = fmaxf(mx1, __shfl_xor_sync(0xffffffffu, mx1, 1));
        mx1 = fmaxf(mx1, __shfl_xor_sync(0xffffffffu, mx1, 2));
        const float mn0 = fmaxf(m0, mx0);
        const float mn1 = fmaxf(m1, mx1);
        const float a0 = __expf(m0 - mn0);
        const float a1 = __expf(m1 - mn1);
        m0 = mn0; m1 = mn1;
        l0 *= a0; l1 *= a1;
#pragma unroll
        for (int nt = 0; nt < 16; nt++) {
            acc[nt][0] *= a0; acc[nt][1] *= a0;
            acc[nt][2] *= a1; acc[nt][3] *= a1;
        }

        float ps0 = 0.0f, ps1 = 0.0f;
#pragma unroll
        for (int nt = 0; nt < 8; nt++) {
            cs[nt][0] = __expf(cs[nt][0] - mn0);
            cs[nt][1] = __expf(cs[nt][1] - mn0);
            cs[nt][2] = __expf(cs[nt][2] - mn1);
            cs[nt][3] = __expf(cs[nt][3] - mn1);
            ps0 += cs[nt][0] + cs[nt][1];
            ps1 += cs[nt][2] + cs[nt][3];
        }
        ps0 += __shfl_xor_sync(0xffffffffu, ps0, 1);
        ps0 += __shfl_xor_sync(0xffffffffu, ps0, 2);
        ps1 += __shfl_xor_sync(0xffffffffu, ps1, 1);
        ps1 += __shfl_xor_sync(0xffffffffu, ps1, 2);
        l0 += ps0; l1 += ps1;

        const int vg = lane >> 3, vr = lane & 7;
#pragma unroll
        for (int ks2 = 0; ks2 < 4; ks2++) {
            uint32_t pahi[4], palo[4];
#pragma unroll
            for (int t = 0; t < 2; t++) {
                const int nt = 2 * ks2 + t;
                const __nv_bfloat16 h0 = __float2bfloat16(cs[nt][0]);
                const __nv_bfloat16 h1 = __float2bfloat16(cs[nt][1]);
                const __nv_bfloat16 h2 = __float2bfloat16(cs[nt][2]);
                const __nv_bfloat16 h3 = __float2bfloat16(cs[nt][3]);
                pahi[2 * t]     = pack_bf16(h0, h1);
                pahi[2 * t + 1] = pack_bf16(h2, h3);
                palo[2 * t]     = pack_bf16(__float2bfloat16(cs[nt][0] - __bfloat162float(h0)),
                                            __float2bfloat16(cs[nt][1] - __bfloat162float(h1)));
                palo[2 * t + 1] = pack_bf16(__float2bfloat16(cs[nt][2] - __bfloat162float(h2)),
                                            __float2bfloat16(cs[nt][3] - __bfloat162float(h3)));
            }
            const uint32_t vrow = (ks2 * 16 + (vg & 1) * 8 + vr) * ATROW + (vg >> 1) * 16;
#pragma unroll
            for (int dg = 0; dg < 8; dg++) {
                uint32_t th[4], tl[4];
                ldsm4t(th, kbuf + SV_HI + vrow + dg * 32);
                ldsm4t(tl, kbuf + SV_LO + vrow + dg * 32);
                mma16816(acc[dg * 2], pahi, th);
                mma16816(acc[dg * 2], palo, th);
                mma16816(acc[dg * 2], pahi, tl);
                mma16816(acc[dg * 2 + 1], pahi, th + 2);
                mma16816(acc[dg * 2 + 1], palo, th + 2);
                mma16816(acc[dg * 2 + 1], pahi, tl + 2);
            }
        }
        __syncthreads();
    }

    const float il0 = 1.0f / l0;
    const float il1 = 1.0f / l1;
    const size_t r0 = ((size_t)b_ * SS + q0) * K2 + nh * 128;
    const size_t r1 = ((size_t)b_ * SS + q1) * K2 + nh * 128;
#pragma unroll
    for (int nt = 0; nt < 16; nt++) {
        const int d = nt * 8 + tq * 2;
        const float f0 = acc[nt][0] * il0, f1 = acc[nt][1] * il0;
        const float f2 = acc[nt][2] * il1, f3 = acc[nt][3] * il1;
        const __nv_bfloat16 h0 = __float2bfloat16(f0), h1 = __float2bfloat16(f1);
        const __nv_bfloat16 h2 = __float2bfloat16(f2), h3 = __float2bfloat16(f3);
        *(uint32_t*)(g_C2 + r0 + d) = pack_bf16(h0, h1);
        *(uint32_t*)(g_C2 + r1 + d) = pack_bf16(h2, h3);
        const __nv_bfloat16 e0 = __float2bfloat16(f0 - __bfloat162float(h0));
        const __nv_bfloat16 e1 = __float2bfloat16(f1 - __bfloat162float(h1));
        const __nv_bfloat16 e2 = __float2bfloat16(f2 - __bfloat162float(h2));
        const __nv_bfloat16 e3 = __float2bfloat16(f3 - __bfloat162float(h3));
        *(uint32_t*)(g_C2 + r0 + 4096 + d) = pack_bf16(e0, e1);
        *(uint32_t*)(g_C2 + r1 + 4096 + d) = pack_bf16(e2, e3);
    }
}

// ====================================================================
extern "C" void kernel_launch(void* const* d_in, const int* in_sizes, int n_in,
                              void* d_out, int out_size)
{
    (void)in_sizes; (void)n_in; (void)out_size;
    const float* hidden   = (const float*)d_in[0];
    const float* residual = (const float*)d_in[1];
    const float* alibi    = (const float*)d_in[2];
    // d_in[3] = attention_mask (causal; handled analytically)
    const float* W_qkv    = (const float*)d_in[4];
    const float* b_qkv    = (const float*)d_in[5];
    const float* W_dense  = (const float*)d_in[6];
    const float* b_dense  = (const float*)d_in[7];
    float* out = (float*)d_out;

    cudaFuncSetAttribute(hgemm_wide_kernel, cudaFuncAttributeMaxDynamicSharedMemorySize, WSM_TOTAL);
    cudaFuncSetAttribute(hgemm_dense_kernel, cudaFuncAttributeMaxDynamicSharedMemorySize, GSM_TOTAL);
    cudaFuncSetAttribute(attn_kernel, cudaFuncAttributeMaxDynamicSharedMemorySize, ATT_SMEM);

    convert_kernel<0><<<16384, 256>>>(hidden);    // hidden  -> A2 [hi|lo]
    convert_kernel<1><<<49152, 256>>>(W_qkv);     // W_qkv   -> W2
    convert_kernel<2><<<16384, 256>>>(W_dense);   // W_dense -> Wd2
    hgemm_wide_kernel<<<1536, 512, WSM_TOTAL>>>(b_qkv);                     // QKV (wide)
    attn_kernel<<<dim3(16, 64), 256, ATT_SMEM>>>(alibi);                    // flash attn (TC)
    hgemm_dense_kernel<<<1024, 256, GSM_TOTAL>>>(b_dense, residual, out);   // dense
}